// round 16
// baseline (speedup 1.0000x reference)
#include <cuda_runtime.h>
#include <cuda_fp16.h>
#include <math.h>
#include <stdint.h>

#define B_    256
#define DV_   2048
#define WH_   196
#define DA_   620
#define DATT_ 1200
#define DOUT_ 1024
#define M_    (B_*WH_)     // 50176 = 392*128
#define CPAD  1280
#define NPAD  1280
#define NKT   10           // 9 full n-tiles of 128 + 1 tail tile of 48

#define RSQ   144                 // smem row stride in BYTES (128 int8 + 16 pad)
#define AOFF  (128*RSQ)           // 18432: B tile offset within stage
#define STG_B (256*RSQ)           // 36864 bytes per stage (A+B)
#define NSTG  3
#define DSMEM (NSTG*STG_B)        // 110592 bytes (2 CTAs/SM)

// ---- device scratch ----
__device__ float g_xavec[B_*DA_];
__device__ float g_c[B_*CPAD];
__device__ float g_lpart[NKT*M_];
__device__ float g_xvatt[B_*DV_];
__device__ __half g_At[(size_t)M_*DV_];        // transpose intermediate
__device__ int8_t g_Aq[(size_t)M_*DV_];        // quantized A
__device__ int8_t g_Wq[(size_t)NPAD*DV_];      // quantized W
__device__ float  g_sA[M_];                    // per-row A scales
__device__ float  g_sW[NPAD];                  // per-row W scales

// ================= helpers =================
__device__ __forceinline__ uint32_t smem_u32(const void* p){
    uint32_t a;
    asm("{ .reg .u64 t; cvta.to.shared.u64 t, %1; cvt.u32.u64 %0, t; }" : "=r"(a) : "l"(p));
    return a;
}
__device__ __forceinline__ void cpa16(uint32_t d, const void* s){
    asm volatile("cp.async.cg.shared.global [%0], [%1], 16;" :: "r"(d), "l"(s) : "memory");
}
__device__ __forceinline__ void ldm4(uint32_t a, uint32_t& r0, uint32_t& r1,
                                     uint32_t& r2, uint32_t& r3){
    asm volatile("ldmatrix.sync.aligned.m8n8.x4.shared.b16 {%0,%1,%2,%3}, [%4];"
        : "=r"(r0), "=r"(r1), "=r"(r2), "=r"(r3) : "r"(a));
}
__device__ __forceinline__ void mma_s8(int* c, uint32_t a0, uint32_t a1,
                                       uint32_t a2, uint32_t a3,
                                       uint32_t b0, uint32_t b1){
    asm volatile(
        "mma.sync.aligned.m16n8k32.row.col.s32.s8.s8.s32 "
        "{%0,%1,%2,%3}, {%4,%5,%6,%7}, {%8,%9}, {%0,%1,%2,%3};"
        : "+r"(c[0]), "+r"(c[1]), "+r"(c[2]), "+r"(c[3])
        : "r"(a0), "r"(a1), "r"(a2), "r"(a3), "r"(b0), "r"(b1));
}

// ================= prep: transpose to fp16 + (z==B_) gather/pad =============
__global__ __launch_bounds__(256) void prep_kernel(
    const float* __restrict__ V, const float* __restrict__ emb,
    const int* __restrict__ ia)
{
    if (blockIdx.z == B_) {
        int base = (blockIdx.y * 64 + blockIdx.x) * 256 + threadIdx.x; // < 114688
        for (int g = base; g < B_*DA_; g += 64*7*256) {
            int b = g / DA_;
            int j = g - b * DA_;
            g_xavec[g] = emb[(size_t)ia[b] * DA_ + j];
        }
        if (base < B_*(CPAD-DATT_)) {
            int b = base / (CPAD-DATT_);
            int j = base - b * (CPAD-DATT_);
            g_c[b*CPAD + DATT_ + j] = 0.f;
        }
        return;
    }
    __shared__ float tile[32][33];
    int tx = threadIdx.x & 31, ty = threadIdx.x >> 5;
    int c0 = blockIdx.x * 32;
    int s0 = blockIdx.y * 32;
    int b  = blockIdx.z;
    const float* src = V + (size_t)b*DV_*WH_;
    #pragma unroll
    for (int i = 0; i < 4; i++) {
        int c = c0 + ty + i*8, s = s0 + tx;
        if (s < WH_) tile[ty + i*8][tx] = src[(size_t)c*WH_ + s];
    }
    __syncthreads();
    #pragma unroll
    for (int i = 0; i < 4; i++) {
        int s = s0 + ty + i*8, c = c0 + tx;
        if (s < WH_)
            g_At[((size_t)b*WH_ + s)*DV_ + c] = __float2half_rn(tile[tx][ty + i*8]);
    }
}

// ================= quantize: blocks [0,M_) -> A rows, [M_,M_+NPAD) -> W rows
__global__ __launch_bounds__(128) void quant_kernel(const float* __restrict__ W)
{
    __shared__ float smax[128];
    __shared__ float sinv[2];
    int r = blockIdx.x;
    int t = threadIdx.x;

    if (r < M_) {
        const __half2* hp = (const __half2*)(g_At + (size_t)r*DV_);  // 1024 half2
        float2 v[8];
        float mx = 0.f;
        #pragma unroll
        for (int j = 0; j < 8; j++) {
            v[j] = __half22float2(hp[j*128 + t]);
            mx = fmaxf(mx, fmaxf(fabsf(v[j].x), fabsf(v[j].y)));
        }
        smax[t] = mx;
        __syncthreads();
        for (int off = 64; off; off >>= 1) {
            if (t < off) smax[t] = fmaxf(smax[t], smax[t + off]);
            __syncthreads();
        }
        if (t == 0) {
            float m = fmaxf(smax[0], 1e-20f);
            g_sA[r] = m / 127.f;
            sinv[0] = 127.f / m;
        }
        __syncthreads();
        float inv = sinv[0];
        uint16_t* dst = (uint16_t*)(g_Aq + (size_t)r*DV_);
        #pragma unroll
        for (int j = 0; j < 8; j++) {
            int q0 = max(-127, min(127, __float2int_rn(v[j].x * inv)));
            int q1 = max(-127, min(127, __float2int_rn(v[j].y * inv)));
            dst[j*128 + t] = (uint16_t)((q0 & 0xff) | ((q1 & 0xff) << 8));
        }
    } else {
        int n = r - M_;
        const float4* fp = (const float4*)(W + (size_t)n*DV_);   // 512 float4
        float4 v[4];
        float mx = 0.f;
        bool valid = (n < DATT_);
        #pragma unroll
        for (int j = 0; j < 4; j++) {
            v[j] = valid ? fp[j*128 + t] : make_float4(0.f,0.f,0.f,0.f);
            mx = fmaxf(mx, fmaxf(fmaxf(fabsf(v[j].x), fabsf(v[j].y)),
                                 fmaxf(fabsf(v[j].z), fabsf(v[j].w))));
        }
        smax[t] = mx;
        __syncthreads();
        for (int off = 64; off; off >>= 1) {
            if (t < off) smax[t] = fmaxf(smax[t], smax[t + off]);
            __syncthreads();
        }
        if (t == 0) {
            float m = fmaxf(smax[0], 1e-20f);
            g_sW[n] = valid ? (m / 127.f) : 0.f;
            sinv[0] = 127.f / m;
        }
        __syncthreads();
        float inv = sinv[0];
        uint32_t* dst = (uint32_t*)(g_Wq + (size_t)n*DV_);
        #pragma unroll
        for (int j = 0; j < 4; j++) {
            int q0 = max(-127, min(127, __float2int_rn(v[j].x * inv)));
            int q1 = max(-127, min(127, __float2int_rn(v[j].y * inv)));
            int q2 = max(-127, min(127, __float2int_rn(v[j].z * inv)));
            int q3 = max(-127, min(127, __float2int_rn(v[j].w * inv)));
            dst[j*128 + t] = (uint32_t)(q0 & 0xff) | ((uint32_t)(q1 & 0xff) << 8)
                           | ((uint32_t)(q2 & 0xff) << 16) | ((uint32_t)(q3 & 0xff) << 24);
        }
    }
}

// ================= small GEMM body =================
__device__ __forceinline__ void gemm_body(
    const float* __restrict__ X, int J,
    const float* __restrict__ Wm, int KO,
    const float* __restrict__ bias, const float* __restrict__ watt,
    float* __restrict__ dst, int dstrd, int mode,
    int bx, int by)
{
    int t = threadIdx.x, lane = t & 31, w = t >> 5;
    int b0  = bx * 16;
    int ko0 = by * 32 + w * 4;

    float acc[16][4];
    #pragma unroll
    for (int i = 0; i < 16; i++)
        #pragma unroll
        for (int q = 0; q < 4; q++) acc[i][q] = 0.f;

    int nIter = (J/4 + 31) / 32;
    for (int it = 0; it < nIter; ++it) {
        int j = it*128 + lane*4;
        bool jv = (j < J);
        float4 wv[4];
        #pragma unroll
        for (int q = 0; q < 4; q++) {
            int ko = ko0 + q;
            if (jv && ko < KO) wv[q] = *(const float4*)&Wm[(size_t)ko*J + j];
            else               wv[q] = make_float4(0.f,0.f,0.f,0.f);
        }
        #pragma unroll
        for (int bl = 0; bl < 16; ++bl) {
            float4 xv = jv ? *(const float4*)&X[(size_t)(b0+bl)*J + j]
                           : make_float4(0.f,0.f,0.f,0.f);
            #pragma unroll
            for (int q = 0; q < 4; q++)
                acc[bl][q] += xv.x*wv[q].x + xv.y*wv[q].y + xv.z*wv[q].z + xv.w*wv[q].w;
        }
    }
    #pragma unroll
    for (int bl = 0; bl < 16; ++bl)
        #pragma unroll
        for (int q = 0; q < 4; q++) {
            float v = acc[bl][q];
            #pragma unroll
            for (int off = 16; off; off >>= 1)
                v += __shfl_xor_sync(0xffffffffu, v, off);
            acc[bl][q] = v;
        }
    #pragma unroll
    for (int a = 0; a < 64; ++a) {
        if (lane == (a & 31)) {
            int bl = a >> 2, q = a & 3;
            int ko = ko0 + q;
            if (ko < KO) {
                float v = acc[bl][q];
                if (mode == 0) v = fmaxf(v + bias[ko], 0.f) * watt[ko];
                else           v = v + bias[ko];
                dst[(size_t)(b0+bl)*dstrd + ko] = v;
            }
        }
    }
}

__global__ __launch_bounds__(256) void cvec_gemm(
    const float* __restrict__ Wm, const float* __restrict__ bias,
    const float* __restrict__ watt)
{
    gemm_body(g_xavec, DA_, Wm, DATT_, bias, watt, g_c, CPAD, 0,
              blockIdx.x, blockIdx.y);
}

__global__ __launch_bounds__(256) void out_gemm(
    const float* __restrict__ W_img, const float* __restrict__ b_img,
    const float* __restrict__ W_ans, const float* __restrict__ b_ans,
    float* __restrict__ out)
{
    if (blockIdx.z == 0)
        gemm_body(g_xvatt, DV_, W_img, DOUT_, b_img, nullptr,
                  out, 2*DOUT_, 1, blockIdx.x, blockIdx.y);
    else
        gemm_body(g_xavec, DA_, W_ans, DOUT_, b_ans, nullptr,
                  out + DOUT_, 2*DOUT_, 1, blockIdx.x, blockIdx.y);
}

// ================= int8 conv GEMM core (templated full/tail) ===============
// k-chunk per stage = 128 int8 (128B rows). 16 main iters, 4 k32 steps each.
template<int MT4, int NT8, int NB, int BJ, int WTM>
__device__ __forceinline__ void conv_body(
    int wm, int wn, int nt, int mt, uint32_t smu,
    const float* bias_s, const float* sw_s,
    const float (*csh)[128], float (*red)[128])
{
    int t = threadIdx.x, lane = t & 31;
    int m0 = mt*128, n0 = nt*128;
    int b0 = m0 / WH_;
    const uint32_t SMEND = smu + NSTG*STG_B;

    // ---- producer: 16B per cp.async; rows of 128B ----
    int row0 = t >> 3, c16 = t & 7;
    const char* apt = (const char*)(g_Aq + (size_t)(m0+row0)*DV_) + c16*16;
    const char* bpt = (const char*)(g_Wq + (size_t)(n0+row0)*DV_) + c16*16;
    uint32_t so = (uint32_t)(row0*RSQ + c16*16);

    auto load_stage = [&](uint32_t base){
        #pragma unroll
        for (int j = 0; j < 8; j++)
            cpa16(base + so + j*(16*RSQ), apt + (size_t)j*(16*DV_));
        #pragma unroll
        for (int j = 0; j < BJ; j++)
            cpa16(base + AOFF + so + j*(16*RSQ), bpt + (size_t)j*(16*DV_));
        apt += 128; bpt += 128;   // next k128 chunk
    };

    // ---- ldmatrix base offsets (bytes) ----
    int jrow = lane & 7;
    int jmat = lane >> 3;
    uint32_t aoff[MT4], boff[NB];
    #pragma unroll
    for (int mt4 = 0; mt4 < MT4; ++mt4)
        aoff[mt4] = (uint32_t)(wm*WTM + mt4*16 + jrow + (jmat & 1)*8)*RSQ
                     + (uint32_t)(jmat >> 1)*16;
    #pragma unroll
    for (int nb = 0; nb < NB; ++nb)
        boff[nb] = AOFF + (uint32_t)(wn*64 + nb*16 + jrow + (jmat & 1)*8)*RSQ
                     + (uint32_t)(jmat >> 1)*16;

    int acc[MT4][NT8][4];
    #pragma unroll
    for (int i = 0; i < MT4; i++)
        #pragma unroll
        for (int j = 0; j < NT8; j++)
            #pragma unroll
            for (int q = 0; q < 4; q++) acc[i][j][q] = 0;

    load_stage(smu);
    asm volatile("cp.async.commit_group;" ::: "memory");
    load_stage(smu + STG_B);
    asm volatile("cp.async.commit_group;" ::: "memory");

    uint32_t ldb = smu + 2u*STG_B;
    uint32_t rdb = smu;

    uint32_t a[2][MT4][4], b[2][NB][4];
    auto ldfrags = [&](int buf, int ks){
        #pragma unroll
        for (int mt4 = 0; mt4 < MT4; ++mt4)
            ldm4(rdb + aoff[mt4] + ks*32,
                 a[buf][mt4][0], a[buf][mt4][1], a[buf][mt4][2], a[buf][mt4][3]);
        #pragma unroll
        for (int nb = 0; nb < NB; ++nb)
            ldm4(rdb + boff[nb] + ks*32,
                 b[buf][nb][0], b[buf][nb][1], b[buf][nb][2], b[buf][nb][3]);
    };

    for (int i = 0; i < DV_/128; ++i) {        // 16 iterations
        asm volatile("cp.async.wait_group 1;" ::: "memory");
        __syncthreads();

        ldfrags(0, 0);
        if (i + 2 < DV_/128) load_stage(ldb);
        asm volatile("cp.async.commit_group;" ::: "memory");
        ldb += STG_B; if (ldb == SMEND) ldb = smu;

        #pragma unroll
        for (int ks = 0; ks < 4; ++ks) {       // k32 steps within k128
            int cur = ks & 1;
            if (ks < 3) ldfrags(cur ^ 1, ks + 1);
            #pragma unroll
            for (int mt4 = 0; mt4 < MT4; ++mt4) {
                #pragma unroll
                for (int nt8 = 0; nt8 < NT8; ++nt8) {
                    int np = nt8 >> 1, sub = nt8 & 1;
                    mma_s8(acc[mt4][nt8],
                           a[cur][mt4][0], a[cur][mt4][1],
                           a[cur][mt4][2], a[cur][mt4][3],
                           b[cur][np][sub], b[cur][np][sub + 2]);
                }
            }
        }
        rdb += STG_B; if (rdb == SMEND) rdb = smu;
    }

    // ---- epilogue: dequant, relu(z+bias)*c, reduce over n ----
    __syncthreads();
    #pragma unroll
    for (int mt4 = 0; mt4 < MT4; ++mt4) {
        int lm0 = wm*WTM + mt4*16 + (lane >> 2);
        int rs0 = (m0 + lm0) / WH_ - b0;
        int rs1 = (m0 + lm0 + 8) / WH_ - b0;
        float sa0 = g_sA[m0 + lm0];
        float sa1 = g_sA[m0 + lm0 + 8];
        float s0 = 0.f, s1 = 0.f;
        #pragma unroll
        for (int nt8 = 0; nt8 < NT8; ++nt8) {
            int ln = wn*64 + nt8*8 + 2*(lane & 3);
            float sw0 = sw_s[ln], sw1 = sw_s[ln+1];
            float bv0 = bias_s[ln], bv1 = bias_s[ln+1];
            s0 += fmaxf((float)acc[mt4][nt8][0]*(sa0*sw0) + bv0, 0.f) * csh[rs0][ln]
                + fmaxf((float)acc[mt4][nt8][1]*(sa0*sw1) + bv1, 0.f) * csh[rs0][ln+1];
            s1 += fmaxf((float)acc[mt4][nt8][2]*(sa1*sw0) + bv0, 0.f) * csh[rs1][ln]
                + fmaxf((float)acc[mt4][nt8][3]*(sa1*sw1) + bv1, 0.f) * csh[rs1][ln+1];
        }
        s0 += __shfl_xor_sync(0xffffffffu, s0, 1);
        s0 += __shfl_xor_sync(0xffffffffu, s0, 2);
        s1 += __shfl_xor_sync(0xffffffffu, s1, 1);
        s1 += __shfl_xor_sync(0xffffffffu, s1, 2);
        if ((lane & 3) == 0) {
            red[wn][lm0]     = s0;
            red[wn][lm0 + 8] = s1;
        }
    }
}

// grid (10, 392), 128 threads, 2 CTAs/SM. Tiles 0-8: 128-wide. Tile 9: 48-wide.
__global__ __launch_bounds__(128, 2) void conv_mma(const float* __restrict__ bc)
{
    extern __shared__ char smc[];
    __shared__ float bias_s[128];
    __shared__ float sw_s[128];
    __shared__ float csh[2][128];
    __shared__ float red[2][128];

    int t = threadIdx.x, w = t >> 5;
    int nt = blockIdx.x, mt = blockIdx.y;
    int m0 = mt*128, n0 = nt*128;
    int b0 = m0 / WH_;

    {
        int k = n0 + t;
        bias_s[t] = (k < DATT_) ? bc[k] : 0.f;
        sw_s[t]   = g_sW[k];
        csh[0][t] = g_c[(size_t)b0*CPAD + k];
        csh[1][t] = g_c[(size_t)min(b0+1, B_-1)*CPAD + k];
    }

    uint32_t smu = smem_u32(smc);

    if (nt < NKT-1) {
        conv_body<4, 8, 4, 8, 64>(w & 1, w >> 1, nt, mt, smu,
                                  bias_s, sw_s, csh, red);
    } else {
        red[1][t] = 0.f;
        conv_body<2, 6, 3, 3, 32>(w, 0, nt, mt, smu,
                                  bias_s, sw_s, csh, red);
    }

    __syncthreads();
    g_lpart[(size_t)nt*M_ + m0 + t] = red[0][t] + red[1][t];
}

// ================= softmax + weighted sum (coalesced, warp-per-channel) ====
__global__ __launch_bounds__(256) void attn_kernel(
    const float* __restrict__ V, const float* __restrict__ batt)
{
    __shared__ float sm[256];
    __shared__ float attn[WH_];
    int b = blockIdx.y;
    int t = threadIdx.x, lane = t & 31, w = t >> 5;

    float v = -3.4e38f;
    if (t < WH_) {
        float s = batt[0];
        #pragma unroll
        for (int kt = 0; kt < NKT; ++kt)
            s += g_lpart[(size_t)kt*M_ + b*WH_ + t];
        v = s;
    }
    sm[t] = v;
    __syncthreads();
    for (int off = 128; off; off >>= 1) {
        if (t < off) sm[t] = fmaxf(sm[t], sm[t + off]);
        __syncthreads();
    }
    float mx = sm[0];
    __syncthreads();
    float e = (t < WH_) ? expf(v - mx) : 0.f;
    sm[t] = e;
    __syncthreads();
    for (int off = 128; off; off >>= 1) {
        if (t < off) sm[t] += sm[t + off];
        __syncthreads();
    }
    float inv = 1.f / sm[0];
    if (t < WH_) attn[t] = e * inv;
    __syncthreads();

    int d0 = blockIdx.x * 128;
    for (int c = w; c < 128; c += 8) {
        const float4* row = (const float4*)&V[((size_t)b*DV_ + d0 + c) * WH_];
        float acc = 0.f;
        for (int s4 = lane; s4 < WH_/4; s4 += 32) {
            float4 x = row[s4];
            acc += x.x*attn[4*s4]   + x.y*attn[4*s4+1]
                 + x.z*attn[4*s4+2] + x.w*attn[4*s4+3];
        }
        #pragma unroll
        for (int off = 16; off; off >>= 1)
            acc += __shfl_xor_sync(0xffffffffu, acc, off);
        if (lane == 0) g_xvatt[(size_t)b*DV_ + d0 + c] = acc;
    }
}

// ============================================================
extern "C" void kernel_launch(void* const* d_in, const int* in_sizes, int n_in,
                              void* d_out, int out_size)
{
    const float* input_v = (const float*)d_in[0];
    const float* emb     = (const float*)d_in[1];
    const float* W_conv  = (const float*)d_in[2];
    const float* b_conv  = (const float*)d_in[3];
    const float* W_lin_a = (const float*)d_in[4];
    const float* b_lin_a = (const float*)d_in[5];
    const float* w_att   = (const float*)d_in[6];
    const float* b_att   = (const float*)d_in[7];
    const float* W_img   = (const float*)d_in[8];
    const float* b_img   = (const float*)d_in[9];
    const float* W_ans   = (const float*)d_in[10];
    const float* b_ans   = (const float*)d_in[11];
    const int*   input_a = (const int*)d_in[12];
    float* out = (float*)d_out;

    cudaFuncSetAttribute(conv_mma, cudaFuncAttributeMaxDynamicSharedMemorySize,
                         DSMEM);

    // slot 1: transpose to fp16 + embedding gather + c-pad
    prep_kernel<<<dim3(DV_/32, (WH_+31)/32, B_+1), 256>>>(input_v, emb, input_a);
    // slot 2: per-row int8 quantization of A (from g_At) and W
    quant_kernel<<<M_ + NPAD, 128>>>(W_conv);
    // slot 3: c[b,k] = relu(xa . W_lin_a^T + b) * w_att
    cvec_gemm<<<dim3(16, (DATT_+31)/32), 256>>>(W_lin_a, b_lin_a, w_att);
    // slot 4: the big GEMM (profiled slot), int8 k32
    conv_mma<<<dim3(NKT, M_/128), 128, DSMEM>>>(b_conv);
    // slot 5
    attn_kernel<<<dim3(DV_/128, B_), 256>>>(input_v, b_att);
    // slot 6: both output GEMMs in one launch
    out_gemm<<<dim3(16, DOUT_/32, 2), 256>>>(W_img, b_img, W_ans, b_ans, out);
}

// round 17
// speedup vs baseline: 2.1228x; 2.1228x over previous
#include <cuda_runtime.h>
#include <cuda_fp16.h>
#include <math.h>
#include <stdint.h>

#define B_    256
#define DV_   2048
#define WH_   196
#define DA_   620
#define DATT_ 1200
#define DOUT_ 1024
#define M_    (B_*WH_)     // 50176 = 392*128
#define CPAD  1280
#define NPAD  1280
#define NKT   10           // 9 full n-tiles of 128 + 1 tail tile of 48

#define RSB   72                  // smem row stride in fp16 (64 data + 8 pad)
#define AOFF  (128*RSB*2)         // 18432 bytes: B tile offset within stage
#define STG_B (256*RSB*2)         // 36864 bytes per stage (A+B)
#define NSTG  3
#define DSMEM (NSTG*STG_B)        // 110592 bytes (2 CTAs/SM)

// ---- device scratch ----
__device__ float g_xavec[B_*DA_];
__device__ float g_c[B_*CPAD];
__device__ float g_lpart[NKT*M_];
__device__ float g_xvatt[B_*DV_];
__device__ __half g_At[(size_t)M_*DV_];
__device__ __half g_Wt[(size_t)NPAD*DV_];

// ================= helpers =================
__device__ __forceinline__ uint32_t smem_u32(const void* p){
    uint32_t a;
    asm("{ .reg .u64 t; cvta.to.shared.u64 t, %1; cvt.u32.u64 %0, t; }" : "=r"(a) : "l"(p));
    return a;
}
__device__ __forceinline__ void cpa16(uint32_t d, const void* s){
    asm volatile("cp.async.cg.shared.global [%0], [%1], 16;" :: "r"(d), "l"(s) : "memory");
}
__device__ __forceinline__ void ldm4(uint32_t a, uint32_t& r0, uint32_t& r1,
                                     uint32_t& r2, uint32_t& r3){
    asm volatile("ldmatrix.sync.aligned.m8n8.x4.shared.b16 {%0,%1,%2,%3}, [%4];"
        : "=r"(r0), "=r"(r1), "=r"(r2), "=r"(r3) : "r"(a));
}
__device__ __forceinline__ void mma_f16f32(float* c, uint32_t a0, uint32_t a1,
                                           uint32_t a2, uint32_t a3,
                                           uint32_t b0, uint32_t b1){
    asm volatile(
        "mma.sync.aligned.m16n8k16.row.col.f32.f16.f16.f32 "
        "{%0,%1,%2,%3}, {%4,%5,%6,%7}, {%8,%9}, {%0,%1,%2,%3};"
        : "+f"(c[0]), "+f"(c[1]), "+f"(c[2]), "+f"(c[3])
        : "r"(a0), "r"(a1), "r"(a2), "r"(a3), "r"(b0), "r"(b1));
}

// ================= prep kernels =================
__global__ __launch_bounds__(256) void init_kernel(
    const float* __restrict__ emb, const int* __restrict__ ia)
{
    int gid = blockIdx.x * 256 + threadIdx.x;
    if (gid < B_*DA_) {
        int b = gid / DA_;
        int j = gid - b * DA_;
        g_xavec[gid] = emb[(size_t)ia[b] * DA_ + j];
    }
    if (gid < B_*(CPAD-DATT_)) {
        int b = gid / (CPAD-DATT_);
        int j = gid - b * (CPAD-DATT_);
        g_c[b*CPAD + DATT_ + j] = 0.f;
    }
}

// fused: z<256 -> transpose input_v batch z to fp16 (half2 stores);
//        z==256 -> convert/pad W_conv
__global__ __launch_bounds__(256) void prep_kernel(
    const float* __restrict__ V, const float* __restrict__ W)
{
    if (blockIdx.z == B_) {
        int base = (blockIdx.y * 64 + blockIdx.x) * 256 + threadIdx.x;
        const int TOT = (NPAD*DV_)/4;       // 655360 quads
        const int STRIDE = 7*64*256;        // 114688
        for (int i = base; i < TOT; i += STRIDE) {
            float4 v = make_float4(0.f,0.f,0.f,0.f);
            if (i < (DATT_*DV_)/4) v = ((const float4*)W)[i];
            __half2 p0 = __floats2half2_rn(v.x, v.y);
            __half2 p1 = __floats2half2_rn(v.z, v.w);
            ((__half2*)g_Wt)[2*i]   = p0;
            ((__half2*)g_Wt)[2*i+1] = p1;
        }
        return;
    }
    __shared__ float tile[32][33];
    int t = threadIdx.x;
    int tx = t & 31, ty = t >> 5;
    int c0 = blockIdx.x * 32;
    int s0 = blockIdx.y * 32;
    int b  = blockIdx.z;
    const float* src = V + (size_t)b*DV_*WH_;
    #pragma unroll
    for (int i = 0; i < 4; i++) {
        int c = c0 + ty + i*8, s = s0 + tx;
        if (s < WH_) tile[ty + i*8][tx] = src[(size_t)c*WH_ + s];
    }
    __syncthreads();
    // write phase: half2 stores (2 consecutive c's per thread)
    int pj   = t & 15;        // c-pair index 0..15
    int srow = t >> 4;        // 0..15
    #pragma unroll
    for (int i = 0; i < 2; i++) {
        int sl = srow + i*16;
        int s  = s0 + sl;
        if (s < WH_) {
            __half2 h = __floats2half2_rn(tile[pj*2][sl], tile[pj*2+1][sl]);
            *(__half2*)&g_At[((size_t)b*WH_ + s)*DV_ + c0 + pj*2] = h;
        }
    }
}

// ================= small GEMM body =================
__device__ __forceinline__ void gemm_body(
    const float* __restrict__ X, int J,
    const float* __restrict__ Wm, int KO,
    const float* __restrict__ bias, const float* __restrict__ watt,
    float* __restrict__ dst, int dstrd, int mode,
    int bx, int by)
{
    int t = threadIdx.x, lane = t & 31, w = t >> 5;
    int b0  = bx * 16;
    int ko0 = by * 32 + w * 4;

    float acc[16][4];
    #pragma unroll
    for (int i = 0; i < 16; i++)
        #pragma unroll
        for (int q = 0; q < 4; q++) acc[i][q] = 0.f;

    int nIter = (J/4 + 31) / 32;
    for (int it = 0; it < nIter; ++it) {
        int j = it*128 + lane*4;
        bool jv = (j < J);
        float4 wv[4];
        #pragma unroll
        for (int q = 0; q < 4; q++) {
            int ko = ko0 + q;
            if (jv && ko < KO) wv[q] = *(const float4*)&Wm[(size_t)ko*J + j];
            else               wv[q] = make_float4(0.f,0.f,0.f,0.f);
        }
        #pragma unroll
        for (int bl = 0; bl < 16; ++bl) {
            float4 xv = jv ? *(const float4*)&X[(size_t)(b0+bl)*J + j]
                           : make_float4(0.f,0.f,0.f,0.f);
            #pragma unroll
            for (int q = 0; q < 4; q++)
                acc[bl][q] += xv.x*wv[q].x + xv.y*wv[q].y + xv.z*wv[q].z + xv.w*wv[q].w;
        }
    }
    #pragma unroll
    for (int bl = 0; bl < 16; ++bl)
        #pragma unroll
        for (int q = 0; q < 4; q++) {
            float v = acc[bl][q];
            #pragma unroll
            for (int off = 16; off; off >>= 1)
                v += __shfl_xor_sync(0xffffffffu, v, off);
            acc[bl][q] = v;
        }
    #pragma unroll
    for (int a = 0; a < 64; ++a) {
        if (lane == (a & 31)) {
            int bl = a >> 2, q = a & 3;
            int ko = ko0 + q;
            if (ko < KO) {
                float v = acc[bl][q];
                if (mode == 0) v = fmaxf(v + bias[ko], 0.f) * watt[ko];
                else           v = v + bias[ko];
                dst[(size_t)(b0+bl)*dstrd + ko] = v;
            }
        }
    }
}

__global__ __launch_bounds__(256) void cvec_gemm(
    const float* __restrict__ Wm, const float* __restrict__ bias,
    const float* __restrict__ watt)
{
    gemm_body(g_xavec, DA_, Wm, DATT_, bias, watt, g_c, CPAD, 0,
              blockIdx.x, blockIdx.y);
}

__global__ __launch_bounds__(256) void out_gemm(
    const float* __restrict__ W_img, const float* __restrict__ b_img,
    const float* __restrict__ W_ans, const float* __restrict__ b_ans,
    float* __restrict__ out)
{
    if (blockIdx.z == 0)
        gemm_body(g_xvatt, DV_, W_img, DOUT_, b_img, nullptr,
                  out, 2*DOUT_, 1, blockIdx.x, blockIdx.y);
    else
        gemm_body(g_xavec, DA_, W_ans, DOUT_, b_ans, nullptr,
                  out + DOUT_, 2*DOUT_, 1, blockIdx.x, blockIdx.y);
}

// ================= conv GEMM core (templated full/tail) =================
template<int MT4, int NT8, int NB, int BJ, int WTM>
__device__ __forceinline__ void conv_body(
    int wm, int wn, int nt, int mt, uint32_t smu,
    const float* bias_s, const float (*csh)[128], float (*red)[128])
{
    int t = threadIdx.x, lane = t & 31;
    int m0 = mt*128, n0 = nt*128;
    int b0 = m0 / WH_;
    const uint32_t SMEND = smu + NSTG*STG_B;

    // ---- producer ----
    int row0 = t >> 3, c16 = t & 7;
    const char* apt = (const char*)(g_At + (size_t)(m0+row0)*DV_ + c16*8);
    const char* bpt = (const char*)(g_Wt + (size_t)(n0+row0)*DV_ + c16*8);
    uint32_t so = (uint32_t)(row0*RSB + c16*8)*2;

    auto load_stage = [&](uint32_t base){
        #pragma unroll
        for (int j = 0; j < 8; j++)
            cpa16(base + so + j*(16*RSB*2), apt + (size_t)j*(16*DV_*2));
        #pragma unroll
        for (int j = 0; j < BJ; j++)
            cpa16(base + AOFF + so + j*(16*RSB*2), bpt + (size_t)j*(16*DV_*2));
        apt += 128; bpt += 128;
    };

    // ---- ldmatrix base offsets ----
    int jrow = lane & 7;
    int jmat = lane >> 3;
    uint32_t aoff[MT4], boff[NB];
    #pragma unroll
    for (int mt4 = 0; mt4 < MT4; ++mt4)
        aoff[mt4] = ((uint32_t)(wm*WTM + mt4*16 + jrow + (jmat & 1)*8)*RSB
                     + (uint32_t)(jmat >> 1)*8)*2;
    #pragma unroll
    for (int nb = 0; nb < NB; ++nb)
        boff[nb] = AOFF + ((uint32_t)(wn*64 + nb*16 + jrow + (jmat & 1)*8)*RSB
                     + (uint32_t)(jmat >> 1)*8)*2;

    float acc[MT4][NT8][4];
    #pragma unroll
    for (int i = 0; i < MT4; i++)
        #pragma unroll
        for (int j = 0; j < NT8; j++)
            #pragma unroll
            for (int q = 0; q < 4; q++) acc[i][j][q] = 0.f;

    load_stage(smu);
    asm volatile("cp.async.commit_group;" ::: "memory");
    load_stage(smu + STG_B);
    asm volatile("cp.async.commit_group;" ::: "memory");

    uint32_t ldb = smu + 2u*STG_B;
    uint32_t rdb = smu;

    uint32_t a[2][MT4][4], b[2][NB][4];
    auto ldfrags = [&](int buf, int ks){
        #pragma unroll
        for (int mt4 = 0; mt4 < MT4; ++mt4)
            ldm4(rdb + aoff[mt4] + ks*32,
                 a[buf][mt4][0], a[buf][mt4][1], a[buf][mt4][2], a[buf][mt4][3]);
        #pragma unroll
        for (int nb = 0; nb < NB; ++nb)
            ldm4(rdb + boff[nb] + ks*32,
                 b[buf][nb][0], b[buf][nb][1], b[buf][nb][2], b[buf][nb][3]);
    };

    for (int i = 0; i < DV_/64; ++i) {
        asm volatile("cp.async.wait_group 1;" ::: "memory");
        __syncthreads();

        ldfrags(0, 0);
        if (i + 2 < DV_/64) load_stage(ldb);
        asm volatile("cp.async.commit_group;" ::: "memory");
        ldb += STG_B; if (ldb == SMEND) ldb = smu;

        #pragma unroll
        for (int ks = 0; ks < 4; ++ks) {
            int cur = ks & 1;
            if (ks < 3) ldfrags(cur ^ 1, ks + 1);
            #pragma unroll
            for (int mt4 = 0; mt4 < MT4; ++mt4) {
                #pragma unroll
                for (int nt8 = 0; nt8 < NT8; ++nt8) {
                    int np = nt8 >> 1, sub = nt8 & 1;
                    mma_f16f32(acc[mt4][nt8],
                               a[cur][mt4][0], a[cur][mt4][1],
                               a[cur][mt4][2], a[cur][mt4][3],
                               b[cur][np][sub], b[cur][np][sub + 2]);
                }
            }
        }
        rdb += STG_B; if (rdb == SMEND) rdb = smu;
    }

    // ---- epilogue: relu(z+bias)*c, reduce over n ----
    __syncthreads();
    #pragma unroll
    for (int mt4 = 0; mt4 < MT4; ++mt4) {
        int lm0 = wm*WTM + mt4*16 + (lane >> 2);
        int rs0 = (m0 + lm0) / WH_ - b0;
        int rs1 = (m0 + lm0 + 8) / WH_ - b0;
        float s0 = 0.f, s1 = 0.f;
        #pragma unroll
        for (int nt8 = 0; nt8 < NT8; ++nt8) {
            int ln = wn*64 + nt8*8 + 2*(lane & 3);
            float bv0 = bias_s[ln], bv1 = bias_s[ln+1];
            s0 += fmaxf(acc[mt4][nt8][0] + bv0, 0.f) * csh[rs0][ln]
                + fmaxf(acc[mt4][nt8][1] + bv1, 0.f) * csh[rs0][ln+1];
            s1 += fmaxf(acc[mt4][nt8][2] + bv0, 0.f) * csh[rs1][ln]
                + fmaxf(acc[mt4][nt8][3] + bv1, 0.f) * csh[rs1][ln+1];
        }
        s0 += __shfl_xor_sync(0xffffffffu, s0, 1);
        s0 += __shfl_xor_sync(0xffffffffu, s0, 2);
        s1 += __shfl_xor_sync(0xffffffffu, s1, 1);
        s1 += __shfl_xor_sync(0xffffffffu, s1, 2);
        if ((lane & 3) == 0) {
            red[wn][lm0]     = s0;
            red[wn][lm0 + 8] = s1;
        }
    }
}

// grid (10, 392), 128 threads, 2 CTAs/SM. Tiles 0-8: 128-wide. Tile 9: 48-wide.
__global__ __launch_bounds__(128, 2) void conv_mma(const float* __restrict__ bc)
{
    extern __shared__ char smc[];
    __shared__ float bias_s[128];
    __shared__ float csh[2][128];
    __shared__ float red[2][128];

    int t = threadIdx.x, w = t >> 5;
    int nt = blockIdx.x, mt = blockIdx.y;
    int m0 = mt*128, n0 = nt*128;
    int b0 = m0 / WH_;

    {
        int k = n0 + t;
        bias_s[t] = (k < DATT_) ? bc[k] : 0.f;
        csh[0][t] = g_c[(size_t)b0*CPAD + k];
        csh[1][t] = g_c[(size_t)min(b0+1, B_-1)*CPAD + k];
    }

    uint32_t smu = smem_u32(smc);

    if (nt < NKT-1) {
        conv_body<4, 8, 4, 8, 64>(w & 1, w >> 1, nt, mt, smu, bias_s, csh, red);
    } else {
        red[1][t] = 0.f;
        conv_body<2, 6, 3, 3, 32>(w, 0, nt, mt, smu, bias_s, csh, red);
    }

    __syncthreads();
    g_lpart[(size_t)nt*M_ + m0 + t] = red[0][t] + red[1][t];
}

// ================= softmax + weighted sum (coalesced, warp-per-channel) ====
__global__ __launch_bounds__(256) void attn_kernel(
    const float* __restrict__ V, const float* __restrict__ batt)
{
    __shared__ float sm[256];
    __shared__ float attn[WH_];
    int b = blockIdx.y;
    int t = threadIdx.x, lane = t & 31, w = t >> 5;

    float v = -3.4e38f;
    if (t < WH_) {
        float s = batt[0];
        #pragma unroll
        for (int kt = 0; kt < NKT; ++kt)
            s += g_lpart[(size_t)kt*M_ + b*WH_ + t];
        v = s;
    }
    sm[t] = v;
    __syncthreads();
    for (int off = 128; off; off >>= 1) {
        if (t < off) sm[t] = fmaxf(sm[t], sm[t + off]);
        __syncthreads();
    }
    float mx = sm[0];
    __syncthreads();
    float e = (t < WH_) ? expf(v - mx) : 0.f;
    sm[t] = e;
    __syncthreads();
    for (int off = 128; off; off >>= 1) {
        if (t < off) sm[t] += sm[t + off];
        __syncthreads();
    }
    float inv = 1.f / sm[0];
    if (t < WH_) attn[t] = e * inv;
    __syncthreads();

    int d0 = blockIdx.x * 128;
    for (int c = w; c < 128; c += 8) {
        const float4* row = (const float4*)&V[((size_t)b*DV_ + d0 + c) * WH_];
        float acc = 0.f;
        for (int s4 = lane; s4 < WH_/4; s4 += 32) {
            float4 x = row[s4];
            acc += x.x*attn[4*s4]   + x.y*attn[4*s4+1]
                 + x.z*attn[4*s4+2] + x.w*attn[4*s4+3];
        }
        #pragma unroll
        for (int off = 16; off; off >>= 1)
            acc += __shfl_xor_sync(0xffffffffu, acc, off);
        if (lane == 0) g_xvatt[(size_t)b*DV_ + d0 + c] = acc;
    }
}

// ============================================================
extern "C" void kernel_launch(void* const* d_in, const int* in_sizes, int n_in,
                              void* d_out, int out_size)
{
    const float* input_v = (const float*)d_in[0];
    const float* emb     = (const float*)d_in[1];
    const float* W_conv  = (const float*)d_in[2];
    const float* b_conv  = (const float*)d_in[3];
    const float* W_lin_a = (const float*)d_in[4];
    const float* b_lin_a = (const float*)d_in[5];
    const float* w_att   = (const float*)d_in[6];
    const float* b_att   = (const float*)d_in[7];
    const float* W_img   = (const float*)d_in[8];
    const float* b_img   = (const float*)d_in[9];
    const float* W_ans   = (const float*)d_in[10];
    const float* b_ans   = (const float*)d_in[11];
    const int*   input_a = (const int*)d_in[12];
    float* out = (float*)d_out;

    cudaFuncSetAttribute(conv_mma, cudaFuncAttributeMaxDynamicSharedMemorySize,
                         DSMEM);

    // slot 1
    init_kernel<<<620, 256>>>(emb, input_a);
    // slot 2: c[b,k] = relu(xa . W_lin_a^T + b) * w_att
    cvec_gemm<<<dim3(16, (DATT_+31)/32), 256>>>(W_lin_a, b_lin_a, w_att);
    // slot 3: transpose (half2 stores) + W conversion fused
    prep_kernel<<<dim3(DV_/32, (WH_+31)/32, B_+1), 256>>>(input_v, W_conv);
    // slot 4: the big GEMM (profiled slot), fp16 k16, tail-trimmed
    conv_mma<<<dim3(NKT, M_/128), 128, DSMEM>>>(b_conv);
    // slot 5
    attn_kernel<<<dim3(DV_/128, B_), 256>>>(input_v, b_att);
    // slot 6: both output GEMMs in one launch
    out_gemm<<<dim3(16, DOUT_/32, 2), 256>>>(W_img, b_img, W_ans, b_ans, out);
}